// round 13
// baseline (speedup 1.0000x reference)
#include <cuda_runtime.h>
#include <float.h>

// Fixed shapes from reference setup_inputs
#define BATCH 4
#define NQ 8192
#define NK 2048
#define CH 128
// Kernel 1 (half-key scan)
#define TPB1 128
#define GQ 8                     // queries per thread
#define SPLIT 16                 // key-split threads per query group
#define QPB 64                   // queries per CTA
#define HKEYS 1024               // keys per half
#define HPAIRS 512               // pairs per half
#define GPT 4                    // 16-key groups per thread
#define NGRP 64                  // groups per half
#define GSTR 66                  // gmin row stride (conflict-free)
// Kernel 2 (merge + gather): one warp per query
#define TPB2 256
#define QPC2 (TPB2 / 32)         // 8 queries per CTA

// scratch: per (half, global query): top-3 candidate (dist s', key idx)
__device__ float g_cd[2][BATCH * NQ][3];
__device__ int   g_ck[2][BATCH * NQ][3];

// packed f32x2 fma (sm_100+)
#define F32X2_FMA(d, a, b, c) \
    asm("fma.rn.f32x2 %0, %1, %2, %3;" : "=l"(d) : "l"(a), "l"(b), "l"(c))

__device__ __forceinline__ unsigned long long packf2(float lo, float hi) {
    unsigned long long r;
    asm("mov.b64 %0, {%1, %2};" : "=l"(r) : "f"(lo), "f"(hi));
    return r;
}
__device__ __forceinline__ float lo32(unsigned long long v) {
    return __uint_as_float((unsigned)v);
}
__device__ __forceinline__ float hi32(unsigned long long v) {
    return __uint_as_float((unsigned)(v >> 32));
}

// packed s' = ||k||^2 - 2 q.k per key pair; order z,y,x.
// The scalar rescan mirrors this exactly (bitwise identity).
__device__ __forceinline__ unsigned long long dist2pk(
    ulonglong2 XY, ulonglong2 ZW,
    unsigned long long qx, unsigned long long qy, unsigned long long qz)
{
    unsigned long long acc;
    F32X2_FMA(acc, qz, ZW.x, ZW.y);
    F32X2_FMA(acc, qy, XY.y, acc);
    F32X2_FMA(acc, qx, XY.x, acc);
    return acc;
}

// Branchless insert of (m, g) into value-sorted triple with parallel ids.
__device__ __forceinline__ void ins3_idx(float m, int g,
                                         float& d0, float& d1, float& d2,
                                         int& i0, int& i1, int& i2)
{
    bool p0 = m < d0;
    float h = fmaxf(m, d0);  d0 = fminf(m, d0);
    int ih = p0 ? i0 : g;    i0 = p0 ? g : i0;
    bool p1 = h < d1;
    float h1 = fmaxf(h, d1); d1 = fminf(h, d1);
    int ih1 = p1 ? i1 : ih;  i1 = p1 ? ih : i1;
    bool p2 = h1 < d2;
    d2 = fminf(h1, d2);      i2 = p2 ? ih1 : i2;
}

// Merge sorted triple (e*, j*) into (d*, i*), keep 3 smallest.
__device__ __forceinline__ void merge_tri_idx(
    float e0, float e1, float e2, int j0, int j1, int j2,
    float& d0, float& d1, float& d2, int& i0, int& i1, int& i2)
{
    bool pd = d0 <= e0;
    float o0 = fminf(d0, e0); int o0i = pd ? i0 : j0;
    float A  = fmaxf(d0, e0); int iA  = pd ? j0 : i0;
    bool pB = d1 <= e1;
    float Bv = fminf(d1, e1); int iB  = pB ? i1 : j1;
    bool pab = A <= Bv;
    float o1 = fminf(A, Bv);  int o1i = pab ? iA : iB;
    float C  = fmaxf(A, Bv);  int iC  = pab ? iB : iA;
    float D  = fmaxf(d1, e1); int iD  = pB ? j1 : i1;
    bool pE = d2 <= e2;
    float E  = fminf(d2, e2); int iE  = pE ? i2 : j2;
    bool pF = D <= E;
    float F  = fminf(D, E);   int iF  = pF ? iD : iE;
    bool pO = C <= F;
    float o2 = fminf(C, F);   int o2i = pO ? iC : iF;
    d0 = o0; d1 = o1; d2 = o2;
    i0 = o0i; i1 = o1i; i2 = o2i;
}

// tie-broken (v,k) insert: lower v wins, equal v -> lower k wins
__device__ __forceinline__ void ins_tb(float v, int k,
                                       float& b0, float& b1, float& b2,
                                       int& k0, int& k1, int& k2)
{
    bool lt2 = (v < b2) || (v == b2 && k < k2);
    if (lt2) {
        bool lt1 = (v < b1) || (v == b1 && k < k1);
        if (lt1) {
            b2 = b1; k2 = k1;
            bool lt0 = (v < b0) || (v == b0 && k < k0);
            if (lt0) { b1 = b0; k1 = k0; b0 = v; k0 = k; }
            else     { b1 = v;  k1 = k; }
        } else { b2 = v; k2 = k; }
    }
}

// ============================ Kernel 1 ==================================
__global__ __launch_bounds__(TPB1, 6)
void knn_half_kernel(const float* __restrict__ xyz_q,
                     const float* __restrict__ xyz_k)
{
    __shared__ ulonglong2 sXY[HPAIRS];       // 8 KB
    __shared__ ulonglong2 sZW[HPAIRS];       // 8 KB
    __shared__ float gmin[QPB * GSTR];       // 16.5 KB (reused for scv/sck)
    __shared__ int   sgrp[QPB][3];

    // aliases into gmin region (valid after selection phase sync)
    float (*scv)[3][3] = (float (*)[3][3])gmin;
    int   (*sck)[3][3] = (int (*)[3][3])(gmin + QPB * 9);

    const int b    = blockIdx.z;
    const int half = blockIdx.y;
    const int q0   = blockIdx.x * QPB;
    const int tid  = threadIdx.x;
    const float* kb    = xyz_k + ((size_t)b * NK + half * HKEYS) * 3;
    const float* qbase = xyz_q + ((size_t)b * NQ + q0) * 3;

    // ---- stage 512 key-pairs (SoA-pair layout for f32x2) ----
    for (int p = tid; p < HPAIRS; p += TPB1) {
        const float2* k2 = (const float2*)(kb + 6 * p);
        float2 A = k2[0];                 // x0 y0
        float2 Bv = k2[1];                // z0 x1
        float2 Cv = k2[2];                // y1 z1
        float w0 = fmaf(A.x, A.x, fmaf(A.y, A.y, Bv.x * Bv.x));
        float w1 = fmaf(Bv.y, Bv.y, fmaf(Cv.x, Cv.x, Cv.y * Cv.y));
        sXY[p] = make_ulonglong2(packf2(A.x, Bv.y), packf2(A.y, Cv.x));
        sZW[p] = make_ulonglong2(packf2(Bv.x, Cv.y), packf2(w0, w1));
    }

    // ---- packed query coefficients (8 queries per thread group member) ----
    const int g = tid >> 4;          // query octet within block (0..7)
    const int L = tid & 15;          // key-split id
    unsigned long long qxp[GQ], qyp[GQ], qzp[GQ];
    #pragma unroll
    for (int t = 0; t < GQ; ++t) {
        const float* qp = qbase + (g * GQ + t) * 3;
        float qx2 = -2.0f * qp[0], qy2 = -2.0f * qp[1], qz2 = -2.0f * qp[2];
        qxp[t] = packf2(qx2, qx2);
        qyp[t] = packf2(qy2, qy2);
        qzp[t] = packf2(qz2, qz2);
    }
    __syncthreads();

    // ---- scan: 4 sixteen-key groups/thread; group-mins -> smem ----
    for (int gg = 0; gg < GPT; ++gg) {
        const int pc0 = (8 * gg) * SPLIT + L;
        float mt[GQ];
        #pragma unroll
        for (int r = 0; r < 8; ++r) {
            ulonglong2 XY = sXY[pc0 + r * SPLIT];   // conflict-free LDS.128
            ulonglong2 ZW = sZW[pc0 + r * SPLIT];
            #pragma unroll
            for (int t = 0; t < GQ; ++t) {
                unsigned long long s2 = dist2pk(XY, ZW, qxp[t], qyp[t], qzp[t]);
                float pm = fminf(lo32(s2), hi32(s2));
                mt[t] = (r == 0) ? pm : fminf(mt[t], pm);
            }
        }
        const int grp = gg * SPLIT + L;             // group id 0..63
        #pragma unroll
        for (int t = 0; t < GQ; ++t)
            gmin[(g * GQ + t) * GSTR + grp] = mt[t];
    }
    __syncthreads();

    // ---- selection: 2 threads/query pick top-3 groups of 64 ----
    {
        const int q = tid >> 1;
        const int h = tid & 1;
        float d0 = FLT_MAX, d1 = FLT_MAX, d2 = FLT_MAX;
        int   i0 = 0, i1 = 0, i2 = 0;
        const float* row = gmin + q * GSTR;
        #pragma unroll 8
        for (int j = 0; j < NGRP / 2; ++j) {
            const int gi = 2 * j + h;               // interleaved: no conflicts
            ins3_idx(row[gi], gi, d0, d1, d2, i0, i1, i2);
        }
        float e0 = __shfl_xor_sync(0xffffffffu, d0, 1);
        float e1 = __shfl_xor_sync(0xffffffffu, d1, 1);
        float e2 = __shfl_xor_sync(0xffffffffu, d2, 1);
        int   j0 = __shfl_xor_sync(0xffffffffu, i0, 1);
        int   j1 = __shfl_xor_sync(0xffffffffu, i1, 1);
        int   j2 = __shfl_xor_sync(0xffffffffu, i2, 1);
        merge_tri_idx(e0, e1, e2, j0, j1, j2, d0, d1, d2, i0, i1, i2);
        if (h == 0) { sgrp[q][0] = i0; sgrp[q][1] = i1; sgrp[q][2] = i2; }
    }
    __syncthreads();   // gmin reads done -> region reusable as scv/sck

    // ---- rescan: 3 groups x 16 keys per query from smem (exact) ----
    for (int task = tid; task < QPB * 3; task += TPB1) {
        const int q    = task / 3;
        const int slot = task - 3 * q;
        const int grp  = sgrp[q][slot];
        const int gg   = grp >> 4;
        const int Ls   = grp & 15;
        const float* qp = qbase + q * 3;
        const float qx2 = -2.0f * qp[0];
        const float qy2 = -2.0f * qp[1];
        const float qz2 = -2.0f * qp[2];
        float v0 = FLT_MAX, v1 = FLT_MAX, v2 = FLT_MAX;
        int   c0 = 0, c1 = 0, c2 = 0;
        #pragma unroll
        for (int r = 0; r < 8; ++r) {
            const int P = (8 * gg + r) * SPLIT + Ls;
            ulonglong2 XY = sXY[P];
            ulonglong2 ZW = sZW[P];
            // scalar mirror of dist2pk: identical op order -> identical bits
            float s0 = fmaf(qx2, lo32(XY.x),
                       fmaf(qy2, lo32(XY.y),
                       fmaf(qz2, lo32(ZW.x), lo32(ZW.y))));
            float s1 = fmaf(qx2, hi32(XY.x),
                       fmaf(qy2, hi32(XY.y),
                       fmaf(qz2, hi32(ZW.x), hi32(ZW.y))));
            const int kidx = half * HKEYS + 2 * P;
            ins3_idx(s0, kidx,     v0, v1, v2, c0, c1, c2);
            ins3_idx(s1, kidx + 1, v0, v1, v2, c0, c1, c2);
        }
        scv[q][slot][0] = v0; scv[q][slot][1] = v1; scv[q][slot][2] = v2;
        sck[q][slot][0] = c0; sck[q][slot][1] = c1; sck[q][slot][2] = c2;
    }
    __syncthreads();

    // ---- per-query: merge 9 candidates, emit top-3 of this half ----
    if (tid < QPB) {
        float b0 = FLT_MAX, b1 = FLT_MAX, b2 = FLT_MAX;
        int   k0 = 0x7FFFFFFF, k1 = 0x7FFFFFFF, k2 = 0x7FFFFFFF;
        #pragma unroll
        for (int s = 0; s < 3; ++s)
            #pragma unroll
            for (int r = 0; r < 3; ++r)
                ins_tb(scv[tid][s][r], sck[tid][s][r], b0, b1, b2, k0, k1, k2);
        const int qg = b * NQ + q0 + tid;
        g_cd[half][qg][0] = b0; g_cd[half][qg][1] = b1; g_cd[half][qg][2] = b2;
        g_ck[half][qg][0] = k0; g_ck[half][qg][1] = k1; g_ck[half][qg][2] = k2;
    }
}

// ============================ Kernel 2 ==================================
// One warp per query: merge the two halves' candidates (warp-uniform, no
// divergence, broadcast loads), compute weights, gather and write.
__global__ __launch_bounds__(TPB2)
void knn_finish_kernel(const float* __restrict__ xyz_q,
                       const float* __restrict__ v_k,
                       float* __restrict__ out)
{
    const int b    = blockIdx.y;
    const int warp = threadIdx.x >> 5;
    const int lane = threadIdx.x & 31;
    const int q    = blockIdx.x * QPC2 + warp;
    const int qg   = b * NQ + q;

    // all lanes redundantly merge the 6 candidates (uniform -> broadcast LDG)
    float b0 = FLT_MAX, b1 = FLT_MAX, b2 = FLT_MAX;
    int   k0 = 0x7FFFFFFF, k1 = 0x7FFFFFFF, k2 = 0x7FFFFFFF;
    #pragma unroll
    for (int hf = 0; hf < 2; ++hf)
        #pragma unroll
        for (int r = 0; r < 3; ++r)
            ins_tb(g_cd[hf][qg][r], g_ck[hf][qg][r], b0, b1, b2, k0, k1, k2);

    const float* qp = xyz_q + (size_t)qg * 3;
    float qq = fmaf(qp[0], qp[0], fmaf(qp[1], qp[1], qp[2] * qp[2]));
    float w0 = 1.0f / fmaxf(b0 + qq, 1e-10f);
    float w1 = 1.0f / fmaxf(b1 + qq, 1e-10f);
    float w2 = 1.0f / fmaxf(b2 + qq, 1e-10f);
    float inv_sum = 1.0f / (w0 + w1 + w2);
    float a0 = w0 * inv_sum, a1 = w1 * inv_sum, a2 = w2 * inv_sum;

    // gather: lane = channel quad; 3 independent coalesced float4 loads
    const float4* vb = (const float4*)(v_k + (size_t)b * NK * CH);
    float4 va = vb[k0 * (CH / 4) + lane];
    float4 vc = vb[k1 * (CH / 4) + lane];
    float4 vd = vb[k2 * (CH / 4) + lane];
    float4 r;
    r.x = a0 * va.x + a1 * vc.x + a2 * vd.x;
    r.y = a0 * va.y + a1 * vc.y + a2 * vd.y;
    r.z = a0 * va.z + a1 * vc.z + a2 * vd.z;
    r.w = a0 * va.w + a1 * vc.w + a2 * vd.w;
    ((float4*)(out + (size_t)qg * CH))[lane] = r;
}

extern "C" void kernel_launch(void* const* d_in, const int* in_sizes, int n_in,
                              void* d_out, int out_size)
{
    const float* xyz_q = (const float*)d_in[0];   // [4, 8192, 3]
    const float* xyz_k = (const float*)d_in[1];   // [4, 2048, 3]
    const float* v_k   = (const float*)d_in[2];   // [4, 2048, 128]
    float* out = (float*)d_out;                   // [4, 8192, 128]

    dim3 grid1(NQ / QPB, 2, BATCH);    // (128, 2, 4) = 1024 CTAs
    knn_half_kernel<<<grid1, TPB1>>>(xyz_q, xyz_k);

    dim3 grid2(NQ / QPC2, BATCH);      // (1024, 4) = 4096 CTAs, 1 warp/query
    knn_finish_kernel<<<grid2, TPB2>>>(xyz_q, v_k, out);
}

// round 15
// speedup vs baseline: 1.1390x; 1.1390x over previous
#include <cuda_runtime.h>
#include <float.h>

// Fixed shapes from reference setup_inputs
#define BATCH 4
#define NQ 8192
#define NK 2048
#define CH 128
// Kernel 1 (half-key scan)
#define TPB1 128
#define GQ 8                     // queries per thread
#define SPLIT 16                 // key-split threads per query group
#define QPB 64                   // queries per CTA
#define HKEYS 1024               // keys per half
#define HPAIRS 512               // pairs per half
#define GPT 4                    // 16-key groups per thread
#define NGRP 64                  // groups per half
#define GSTR 66                  // gmin row stride (conflict-free)
// Kernel 2 (merge + gather): one warp per query
#define TPB2 256
#define QPC2 (TPB2 / 32)         // 8 queries per CTA

// scratch: per (half, global query): sorted top-3 (dist s', key idx bits).
// Padded to 4 entries (32 B) so each record is 16-byte aligned for LDG.128.
__device__ float2 g_c[2][BATCH * NQ][4];

// packed f32x2 fma (sm_100+)
#define F32X2_FMA(d, a, b, c) \
    asm("fma.rn.f32x2 %0, %1, %2, %3;" : "=l"(d) : "l"(a), "l"(b), "l"(c))

__device__ __forceinline__ unsigned long long packf2(float lo, float hi) {
    unsigned long long r;
    asm("mov.b64 %0, {%1, %2};" : "=l"(r) : "f"(lo), "f"(hi));
    return r;
}
__device__ __forceinline__ float lo32(unsigned long long v) {
    return __uint_as_float((unsigned)v);
}
__device__ __forceinline__ float hi32(unsigned long long v) {
    return __uint_as_float((unsigned)(v >> 32));
}

// packed s' = ||k||^2 - 2 q.k per key pair; order z,y,x.
// The scalar rescan mirrors this exactly (bitwise identity).
__device__ __forceinline__ unsigned long long dist2pk(
    ulonglong2 XY, ulonglong2 ZW,
    unsigned long long qx, unsigned long long qy, unsigned long long qz)
{
    unsigned long long acc;
    F32X2_FMA(acc, qz, ZW.x, ZW.y);
    F32X2_FMA(acc, qy, XY.y, acc);
    F32X2_FMA(acc, qx, XY.x, acc);
    return acc;
}

// Branchless insert of (m, g) into value-sorted triple with parallel ids.
__device__ __forceinline__ void ins3_idx(float m, int g,
                                         float& d0, float& d1, float& d2,
                                         int& i0, int& i1, int& i2)
{
    bool p0 = m < d0;
    float h = fmaxf(m, d0);  d0 = fminf(m, d0);
    int ih = p0 ? i0 : g;    i0 = p0 ? g : i0;
    bool p1 = h < d1;
    float h1 = fmaxf(h, d1); d1 = fminf(h, d1);
    int ih1 = p1 ? i1 : ih;  i1 = p1 ? ih : i1;
    bool p2 = h1 < d2;
    d2 = fminf(h1, d2);      i2 = p2 ? ih1 : i2;
}

// Merge sorted triple (e*, j*) into (d*, i*), keep 3 smallest.
// Prefers d-side on exact ties (use d = lower-index source).
__device__ __forceinline__ void merge_tri_idx(
    float e0, float e1, float e2, int j0, int j1, int j2,
    float& d0, float& d1, float& d2, int& i0, int& i1, int& i2)
{
    bool pd = d0 <= e0;
    float o0 = fminf(d0, e0); int o0i = pd ? i0 : j0;
    float A  = fmaxf(d0, e0); int iA  = pd ? j0 : i0;
    bool pB = d1 <= e1;
    float Bv = fminf(d1, e1); int iB  = pB ? i1 : j1;
    bool pab = A <= Bv;
    float o1 = fminf(A, Bv);  int o1i = pab ? iA : iB;
    float C  = fmaxf(A, Bv);  int iC  = pab ? iB : iA;
    float D  = fmaxf(d1, e1); int iD  = pB ? j1 : i1;
    bool pE = d2 <= e2;
    float E  = fminf(d2, e2); int iE  = pE ? i2 : j2;
    bool pF = D <= E;
    float F  = fminf(D, E);   int iF  = pF ? iD : iE;
    bool pO = C <= F;
    float o2 = fminf(C, F);   int o2i = pO ? iC : iF;
    d0 = o0; d1 = o1; d2 = o2;
    i0 = o0i; i1 = o1i; i2 = o2i;
}

// tie-broken (v,k) insert: lower v wins, equal v -> lower k wins
__device__ __forceinline__ void ins_tb(float v, int k,
                                       float& b0, float& b1, float& b2,
                                       int& k0, int& k1, int& k2)
{
    bool lt2 = (v < b2) || (v == b2 && k < k2);
    if (lt2) {
        bool lt1 = (v < b1) || (v == b1 && k < k1);
        if (lt1) {
            b2 = b1; k2 = k1;
            bool lt0 = (v < b0) || (v == b0 && k < k0);
            if (lt0) { b1 = b0; k1 = k0; b0 = v; k0 = k; }
            else     { b1 = v;  k1 = k; }
        } else { b2 = v; k2 = k; }
    }
}

// ============================ Kernel 1 ==================================
__global__ __launch_bounds__(TPB1, 6)
void knn_half_kernel(const float* __restrict__ xyz_q,
                     const float* __restrict__ xyz_k)
{
    __shared__ ulonglong2 sXY[HPAIRS];       // 8 KB
    __shared__ ulonglong2 sZW[HPAIRS];       // 8 KB
    __shared__ float gmin[QPB * GSTR];       // 16.5 KB (reused for scv/sck)
    __shared__ int   sgrp[QPB][3];

    // aliases into gmin region (valid after selection phase sync)
    float (*scv)[3][3] = (float (*)[3][3])gmin;
    int   (*sck)[3][3] = (int (*)[3][3])(gmin + QPB * 9);

    const int b    = blockIdx.z;
    const int half = blockIdx.y;
    const int q0   = blockIdx.x * QPB;
    const int tid  = threadIdx.x;
    const float* kb    = xyz_k + ((size_t)b * NK + half * HKEYS) * 3;
    const float* qbase = xyz_q + ((size_t)b * NQ + q0) * 3;

    // ---- stage 512 key-pairs (SoA-pair layout for f32x2) ----
    for (int p = tid; p < HPAIRS; p += TPB1) {
        const float2* k2 = (const float2*)(kb + 6 * p);
        float2 A = k2[0];                 // x0 y0
        float2 Bv = k2[1];                // z0 x1
        float2 Cv = k2[2];                // y1 z1
        float w0 = fmaf(A.x, A.x, fmaf(A.y, A.y, Bv.x * Bv.x));
        float w1 = fmaf(Bv.y, Bv.y, fmaf(Cv.x, Cv.x, Cv.y * Cv.y));
        sXY[p] = make_ulonglong2(packf2(A.x, Bv.y), packf2(A.y, Cv.x));
        sZW[p] = make_ulonglong2(packf2(Bv.x, Cv.y), packf2(w0, w1));
    }

    // ---- packed query coefficients (8 queries per thread group member) ----
    const int g = tid >> 4;          // query octet within block (0..7)
    const int L = tid & 15;          // key-split id
    unsigned long long qxp[GQ], qyp[GQ], qzp[GQ];
    #pragma unroll
    for (int t = 0; t < GQ; ++t) {
        const float* qp = qbase + (g * GQ + t) * 3;
        float qx2 = -2.0f * qp[0], qy2 = -2.0f * qp[1], qz2 = -2.0f * qp[2];
        qxp[t] = packf2(qx2, qx2);
        qyp[t] = packf2(qy2, qy2);
        qzp[t] = packf2(qz2, qz2);
    }
    __syncthreads();

    // ---- scan: 4 sixteen-key groups/thread; group-mins -> smem ----
    for (int gg = 0; gg < GPT; ++gg) {
        const int pc0 = (8 * gg) * SPLIT + L;
        float mt[GQ];
        #pragma unroll
        for (int r = 0; r < 8; ++r) {
            ulonglong2 XY = sXY[pc0 + r * SPLIT];   // conflict-free LDS.128
            ulonglong2 ZW = sZW[pc0 + r * SPLIT];
            #pragma unroll
            for (int t = 0; t < GQ; ++t) {
                unsigned long long s2 = dist2pk(XY, ZW, qxp[t], qyp[t], qzp[t]);
                float pm = fminf(lo32(s2), hi32(s2));
                mt[t] = (r == 0) ? pm : fminf(mt[t], pm);
            }
        }
        const int grp = gg * SPLIT + L;             // group id 0..63
        #pragma unroll
        for (int t = 0; t < GQ; ++t)
            gmin[(g * GQ + t) * GSTR + grp] = mt[t];
    }
    __syncthreads();

    // ---- selection: 2 threads/query pick top-3 groups of 64 ----
    {
        const int q = tid >> 1;
        const int h = tid & 1;
        float d0 = FLT_MAX, d1 = FLT_MAX, d2 = FLT_MAX;
        int   i0 = 0, i1 = 0, i2 = 0;
        const float* row = gmin + q * GSTR;
        #pragma unroll 8
        for (int j = 0; j < NGRP / 2; ++j) {
            const int gi = 2 * j + h;               // interleaved: no conflicts
            ins3_idx(row[gi], gi, d0, d1, d2, i0, i1, i2);
        }
        float e0 = __shfl_xor_sync(0xffffffffu, d0, 1);
        float e1 = __shfl_xor_sync(0xffffffffu, d1, 1);
        float e2 = __shfl_xor_sync(0xffffffffu, d2, 1);
        int   j0 = __shfl_xor_sync(0xffffffffu, i0, 1);
        int   j1 = __shfl_xor_sync(0xffffffffu, i1, 1);
        int   j2 = __shfl_xor_sync(0xffffffffu, i2, 1);
        merge_tri_idx(e0, e1, e2, j0, j1, j2, d0, d1, d2, i0, i1, i2);
        if (h == 0) { sgrp[q][0] = i0; sgrp[q][1] = i1; sgrp[q][2] = i2; }
    }
    __syncthreads();   // gmin reads done -> region reusable as scv/sck

    // ---- rescan: 3 groups x 16 keys per query from smem (exact) ----
    for (int task = tid; task < QPB * 3; task += TPB1) {
        const int q    = task / 3;
        const int slot = task - 3 * q;
        const int grp  = sgrp[q][slot];
        const int gg   = grp >> 4;
        const int Ls   = grp & 15;
        const float* qp = qbase + q * 3;
        const float qx2 = -2.0f * qp[0];
        const float qy2 = -2.0f * qp[1];
        const float qz2 = -2.0f * qp[2];
        float v0 = FLT_MAX, v1 = FLT_MAX, v2 = FLT_MAX;
        int   c0 = 0, c1 = 0, c2 = 0;
        #pragma unroll
        for (int r = 0; r < 8; ++r) {
            const int P = (8 * gg + r) * SPLIT + Ls;
            ulonglong2 XY = sXY[P];
            ulonglong2 ZW = sZW[P];
            // scalar mirror of dist2pk: identical op order -> identical bits
            float s0 = fmaf(qx2, lo32(XY.x),
                       fmaf(qy2, lo32(XY.y),
                       fmaf(qz2, lo32(ZW.x), lo32(ZW.y))));
            float s1 = fmaf(qx2, hi32(XY.x),
                       fmaf(qy2, hi32(XY.y),
                       fmaf(qz2, hi32(ZW.x), hi32(ZW.y))));
            const int kidx = half * HKEYS + 2 * P;
            ins3_idx(s0, kidx,     v0, v1, v2, c0, c1, c2);
            ins3_idx(s1, kidx + 1, v0, v1, v2, c0, c1, c2);
        }
        scv[q][slot][0] = v0; scv[q][slot][1] = v1; scv[q][slot][2] = v2;
        sck[q][slot][0] = c0; sck[q][slot][1] = c1; sck[q][slot][2] = c2;
    }
    __syncthreads();

    // ---- per-query: merge 9 candidates, emit sorted top-3 (packed) ----
    if (tid < QPB) {
        float b0 = FLT_MAX, b1 = FLT_MAX, b2 = FLT_MAX;
        int   k0 = 0x7FFFFFFF, k1 = 0x7FFFFFFF, k2 = 0x7FFFFFFF;
        #pragma unroll
        for (int s = 0; s < 3; ++s)
            #pragma unroll
            for (int r = 0; r < 3; ++r)
                ins_tb(scv[tid][s][r], sck[tid][s][r], b0, b1, b2, k0, k1, k2);
        const int qg = b * NQ + q0 + tid;
        // 32-byte record, 16B-aligned: one STG.128 + one STG.64
        float4* dst = (float4*)&g_c[half][qg][0];
        dst[0] = make_float4(b0, __int_as_float(k0), b1, __int_as_float(k1));
        ((float2*)dst)[2] = make_float2(b2, __int_as_float(k2));
    }
}

// ============================ Kernel 2 ==================================
// One warp per query: branchless merge of the two sorted half-triples
// (half 0 passed as d-side -> ties prefer lower index), single-reciprocal
// weights, coalesced gather + write.
__global__ __launch_bounds__(TPB2)
void knn_finish_kernel(const float* __restrict__ xyz_q,
                       const float* __restrict__ v_k,
                       float* __restrict__ out)
{
    const int b    = blockIdx.y;
    const int warp = threadIdx.x >> 5;
    const int lane = threadIdx.x & 31;
    const int q    = blockIdx.x * QPC2 + warp;
    const int qg   = b * NQ + q;

    // 4 warp-uniform loads (LDG.128 + LDG.64 per half), high MLP
    const float4* c0p = (const float4*)&g_c[0][qg][0];
    const float4* c1p = (const float4*)&g_c[1][qg][0];
    float4 h0a = c0p[0];                        // d0, i0, d1, i1
    float2 h0b = ((const float2*)c0p)[2];       // d2, i2
    float4 h1a = c1p[0];
    float2 h1b = ((const float2*)c1p)[2];

    float d0 = h0a.x, d1 = h0a.z, d2 = h0b.x;
    int   i0 = __float_as_int(h0a.y), i1 = __float_as_int(h0a.w),
          i2 = __float_as_int(h0b.y);
    merge_tri_idx(h1a.x, h1a.z, h1b.x,
                  __float_as_int(h1a.y), __float_as_int(h1a.w),
                  __float_as_int(h1b.y),
                  d0, d1, d2, i0, i1, i2);

    const float* qp = xyz_q + (size_t)qg * 3;
    float qq = fmaf(qp[0], qp[0], fmaf(qp[1], qp[1], qp[2] * qp[2]));
    float e0 = fmaxf(d0 + qq, 1e-10f);
    float e1 = fmaxf(d1 + qq, 1e-10f);
    float e2 = fmaxf(d2 + qq, 1e-10f);
    // a_i = (prod of others) / (e0e1 + e1e2 + e2e0): one reciprocal
    float p01 = e0 * e1, p12 = e1 * e2, p20 = e2 * e0;
    float invS = 1.0f / (p01 + p12 + p20);
    float a0 = p12 * invS, a1 = p20 * invS, a2 = p01 * invS;

    // gather: lane = channel quad; 3 independent coalesced float4 loads
    const float4* vb = (const float4*)(v_k + (size_t)b * NK * CH);
    float4 va = vb[i0 * (CH / 4) + lane];
    float4 vc = vb[i1 * (CH / 4) + lane];
    float4 vd = vb[i2 * (CH / 4) + lane];
    float4 r;
    r.x = a0 * va.x + a1 * vc.x + a2 * vd.x;
    r.y = a0 * va.y + a1 * vc.y + a2 * vd.y;
    r.z = a0 * va.z + a1 * vc.z + a2 * vd.z;
    r.w = a0 * va.w + a1 * vc.w + a2 * vd.w;
    ((float4*)(out + (size_t)qg * CH))[lane] = r;
}

extern "C" void kernel_launch(void* const* d_in, const int* in_sizes, int n_in,
                              void* d_out, int out_size)
{
    const float* xyz_q = (const float*)d_in[0];   // [4, 8192, 3]
    const float* xyz_k = (const float*)d_in[1];   // [4, 2048, 3]
    const float* v_k   = (const float*)d_in[2];   // [4, 2048, 128]
    float* out = (float*)d_out;                   // [4, 8192, 128]

    dim3 grid1(NQ / QPB, 2, BATCH);    // (128, 2, 4) = 1024 CTAs
    knn_half_kernel<<<grid1, TPB1>>>(xyz_q, xyz_k);

    dim3 grid2(NQ / QPC2, BATCH);      // (1024, 4) = 4096 CTAs, 1 warp/query
    knn_finish_kernel<<<grid2, TPB2>>>(xyz_q, v_k, out);
}

// round 16
// speedup vs baseline: 1.1511x; 1.0106x over previous
#include <cuda_runtime.h>
#include <float.h>

// Fixed shapes from reference setup_inputs
#define BATCH 4
#define NQ 8192
#define NK 2048
#define CH 128
// Kernel 1 (half-key scan)
#define TPB1 128
#define GQ 8                     // queries per thread
#define SPLIT 16                 // key-split threads per query group
#define QPB 64                   // queries per CTA
#define HKEYS 1024               // keys per half
#define HPAIRS 512               // pairs per half
#define GPT 4                    // 16-key groups per thread
#define NGRP 64                  // groups per half
#define GSTR 66                  // gmin row stride (conflict-free)
// Kernel 2 (merge + gather)
#define TPB2 256
#define QW 4                     // queries per warp
#define QPC2 ((TPB2 / 32) * QW)  // 32 queries per CTA

// scratch: per (half, global query), 32-byte 16B-aligned record:
// [0]=(d0,i0) [1]=(d1,i1) [2]=(d2,i2) [3]=(qq, pad)
__device__ float2 g_c[2][BATCH * NQ][4];

// packed f32x2 fma (sm_100+)
#define F32X2_FMA(d, a, b, c) \
    asm("fma.rn.f32x2 %0, %1, %2, %3;" : "=l"(d) : "l"(a), "l"(b), "l"(c))

__device__ __forceinline__ unsigned long long packf2(float lo, float hi) {
    unsigned long long r;
    asm("mov.b64 %0, {%1, %2};" : "=l"(r) : "f"(lo), "f"(hi));
    return r;
}
__device__ __forceinline__ float lo32(unsigned long long v) {
    return __uint_as_float((unsigned)v);
}
__device__ __forceinline__ float hi32(unsigned long long v) {
    return __uint_as_float((unsigned)(v >> 32));
}

// packed s' = ||k||^2 - 2 q.k per key pair; order z,y,x.
// The scalar rescan mirrors this exactly (bitwise identity).
__device__ __forceinline__ unsigned long long dist2pk(
    ulonglong2 XY, ulonglong2 ZW,
    unsigned long long qx, unsigned long long qy, unsigned long long qz)
{
    unsigned long long acc;
    F32X2_FMA(acc, qz, ZW.x, ZW.y);
    F32X2_FMA(acc, qy, XY.y, acc);
    F32X2_FMA(acc, qx, XY.x, acc);
    return acc;
}

// Branchless insert of (m, g) into value-sorted triple with parallel ids.
__device__ __forceinline__ void ins3_idx(float m, int g,
                                         float& d0, float& d1, float& d2,
                                         int& i0, int& i1, int& i2)
{
    bool p0 = m < d0;
    float h = fmaxf(m, d0);  d0 = fminf(m, d0);
    int ih = p0 ? i0 : g;    i0 = p0 ? g : i0;
    bool p1 = h < d1;
    float h1 = fmaxf(h, d1); d1 = fminf(h, d1);
    int ih1 = p1 ? i1 : ih;  i1 = p1 ? ih : i1;
    bool p2 = h1 < d2;
    d2 = fminf(h1, d2);      i2 = p2 ? ih1 : i2;
}

// Merge sorted triple (e*, j*) into (d*, i*), keep 3 smallest.
// Prefers d-side on exact ties (use d = lower-index source).
__device__ __forceinline__ void merge_tri_idx(
    float e0, float e1, float e2, int j0, int j1, int j2,
    float& d0, float& d1, float& d2, int& i0, int& i1, int& i2)
{
    bool pd = d0 <= e0;
    float o0 = fminf(d0, e0); int o0i = pd ? i0 : j0;
    float A  = fmaxf(d0, e0); int iA  = pd ? j0 : i0;
    bool pB = d1 <= e1;
    float Bv = fminf(d1, e1); int iB  = pB ? i1 : j1;
    bool pab = A <= Bv;
    float o1 = fminf(A, Bv);  int o1i = pab ? iA : iB;
    float C  = fmaxf(A, Bv);  int iC  = pab ? iB : iA;
    float D  = fmaxf(d1, e1); int iD  = pB ? j1 : i1;
    bool pE = d2 <= e2;
    float E  = fminf(d2, e2); int iE  = pE ? i2 : j2;
    bool pF = D <= E;
    float F  = fminf(D, E);   int iF  = pF ? iD : iE;
    bool pO = C <= F;
    float o2 = fminf(C, F);   int o2i = pO ? iC : iF;
    d0 = o0; d1 = o1; d2 = o2;
    i0 = o0i; i1 = o1i; i2 = o2i;
}

// tie-broken (v,k) insert: lower v wins, equal v -> lower k wins
__device__ __forceinline__ void ins_tb(float v, int k,
                                       float& b0, float& b1, float& b2,
                                       int& k0, int& k1, int& k2)
{
    bool lt2 = (v < b2) || (v == b2 && k < k2);
    if (lt2) {
        bool lt1 = (v < b1) || (v == b1 && k < k1);
        if (lt1) {
            b2 = b1; k2 = k1;
            bool lt0 = (v < b0) || (v == b0 && k < k0);
            if (lt0) { b1 = b0; k1 = k0; b0 = v; k0 = k; }
            else     { b1 = v;  k1 = k; }
        } else { b2 = v; k2 = k; }
    }
}

// ============================ Kernel 1 ==================================
__global__ __launch_bounds__(TPB1, 6)
void knn_half_kernel(const float* __restrict__ xyz_q,
                     const float* __restrict__ xyz_k)
{
    __shared__ ulonglong2 sXY[HPAIRS];       // 8 KB
    __shared__ ulonglong2 sZW[HPAIRS];       // 8 KB
    __shared__ float gmin[QPB * GSTR];       // 16.5 KB (reused for scv/sck)
    __shared__ int   sgrp[QPB][3];

    // aliases into gmin region (valid after selection phase sync)
    float (*scv)[3][3] = (float (*)[3][3])gmin;
    int   (*sck)[3][3] = (int (*)[3][3])(gmin + QPB * 9);

    const int b    = blockIdx.z;
    const int half = blockIdx.y;
    const int q0   = blockIdx.x * QPB;
    const int tid  = threadIdx.x;
    const float* kb    = xyz_k + ((size_t)b * NK + half * HKEYS) * 3;
    const float* qbase = xyz_q + ((size_t)b * NQ + q0) * 3;

    // ---- stage 512 key-pairs (SoA-pair layout for f32x2) ----
    for (int p = tid; p < HPAIRS; p += TPB1) {
        const float2* k2 = (const float2*)(kb + 6 * p);
        float2 A = k2[0];                 // x0 y0
        float2 Bv = k2[1];                // z0 x1
        float2 Cv = k2[2];                // y1 z1
        float w0 = fmaf(A.x, A.x, fmaf(A.y, A.y, Bv.x * Bv.x));
        float w1 = fmaf(Bv.y, Bv.y, fmaf(Cv.x, Cv.x, Cv.y * Cv.y));
        sXY[p] = make_ulonglong2(packf2(A.x, Bv.y), packf2(A.y, Cv.x));
        sZW[p] = make_ulonglong2(packf2(Bv.x, Cv.y), packf2(w0, w1));
    }

    // ---- packed query coefficients (8 queries per thread group member) ----
    const int g = tid >> 4;          // query octet within block (0..7)
    const int L = tid & 15;          // key-split id
    unsigned long long qxp[GQ], qyp[GQ], qzp[GQ];
    #pragma unroll
    for (int t = 0; t < GQ; ++t) {
        const float* qp = qbase + (g * GQ + t) * 3;
        float qx2 = -2.0f * qp[0], qy2 = -2.0f * qp[1], qz2 = -2.0f * qp[2];
        qxp[t] = packf2(qx2, qx2);
        qyp[t] = packf2(qy2, qy2);
        qzp[t] = packf2(qz2, qz2);
    }
    __syncthreads();

    // ---- scan: 4 sixteen-key groups/thread; group-mins -> smem ----
    for (int gg = 0; gg < GPT; ++gg) {
        const int pc0 = (8 * gg) * SPLIT + L;
        float mt[GQ];
        #pragma unroll
        for (int r = 0; r < 8; ++r) {
            ulonglong2 XY = sXY[pc0 + r * SPLIT];   // conflict-free LDS.128
            ulonglong2 ZW = sZW[pc0 + r * SPLIT];
            #pragma unroll
            for (int t = 0; t < GQ; ++t) {
                unsigned long long s2 = dist2pk(XY, ZW, qxp[t], qyp[t], qzp[t]);
                float pm = fminf(lo32(s2), hi32(s2));
                mt[t] = (r == 0) ? pm : fminf(mt[t], pm);
            }
        }
        const int grp = gg * SPLIT + L;             // group id 0..63
        #pragma unroll
        for (int t = 0; t < GQ; ++t)
            gmin[(g * GQ + t) * GSTR + grp] = mt[t];
    }
    __syncthreads();

    // ---- selection: 2 threads/query pick top-3 groups of 64 ----
    {
        const int q = tid >> 1;
        const int h = tid & 1;
        float d0 = FLT_MAX, d1 = FLT_MAX, d2 = FLT_MAX;
        int   i0 = 0, i1 = 0, i2 = 0;
        const float* row = gmin + q * GSTR;
        #pragma unroll 8
        for (int j = 0; j < NGRP / 2; ++j) {
            const int gi = 2 * j + h;               // interleaved: no conflicts
            ins3_idx(row[gi], gi, d0, d1, d2, i0, i1, i2);
        }
        float e0 = __shfl_xor_sync(0xffffffffu, d0, 1);
        float e1 = __shfl_xor_sync(0xffffffffu, d1, 1);
        float e2 = __shfl_xor_sync(0xffffffffu, d2, 1);
        int   j0 = __shfl_xor_sync(0xffffffffu, i0, 1);
        int   j1 = __shfl_xor_sync(0xffffffffu, i1, 1);
        int   j2 = __shfl_xor_sync(0xffffffffu, i2, 1);
        merge_tri_idx(e0, e1, e2, j0, j1, j2, d0, d1, d2, i0, i1, i2);
        if (h == 0) { sgrp[q][0] = i0; sgrp[q][1] = i1; sgrp[q][2] = i2; }
    }
    __syncthreads();   // gmin reads done -> region reusable as scv/sck

    // ---- rescan: 3 groups x 16 keys per query from smem (exact) ----
    for (int task = tid; task < QPB * 3; task += TPB1) {
        const int q    = task / 3;
        const int slot = task - 3 * q;
        const int grp  = sgrp[q][slot];
        const int gg   = grp >> 4;
        const int Ls   = grp & 15;
        const float* qp = qbase + q * 3;
        const float qx2 = -2.0f * qp[0];
        const float qy2 = -2.0f * qp[1];
        const float qz2 = -2.0f * qp[2];
        float v0 = FLT_MAX, v1 = FLT_MAX, v2 = FLT_MAX;
        int   c0 = 0, c1 = 0, c2 = 0;
        #pragma unroll
        for (int r = 0; r < 8; ++r) {
            const int P = (8 * gg + r) * SPLIT + Ls;
            ulonglong2 XY = sXY[P];
            ulonglong2 ZW = sZW[P];
            // scalar mirror of dist2pk: identical op order -> identical bits
            float s0 = fmaf(qx2, lo32(XY.x),
                       fmaf(qy2, lo32(XY.y),
                       fmaf(qz2, lo32(ZW.x), lo32(ZW.y))));
            float s1 = fmaf(qx2, hi32(XY.x),
                       fmaf(qy2, hi32(XY.y),
                       fmaf(qz2, hi32(ZW.x), hi32(ZW.y))));
            const int kidx = half * HKEYS + 2 * P;
            ins3_idx(s0, kidx,     v0, v1, v2, c0, c1, c2);
            ins3_idx(s1, kidx + 1, v0, v1, v2, c0, c1, c2);
        }
        scv[q][slot][0] = v0; scv[q][slot][1] = v1; scv[q][slot][2] = v2;
        sck[q][slot][0] = c0; sck[q][slot][1] = c1; sck[q][slot][2] = c2;
    }
    __syncthreads();

    // ---- per-query: merge 9 candidates, emit sorted top-3 + qq (packed) ----
    if (tid < QPB) {
        float b0 = FLT_MAX, b1 = FLT_MAX, b2 = FLT_MAX;
        int   k0 = 0x7FFFFFFF, k1 = 0x7FFFFFFF, k2 = 0x7FFFFFFF;
        #pragma unroll
        for (int s = 0; s < 3; ++s)
            #pragma unroll
            for (int r = 0; r < 3; ++r)
                ins_tb(scv[tid][s][r], sck[tid][s][r], b0, b1, b2, k0, k1, k2);
        const float* qp = qbase + tid * 3;
        float qq = fmaf(qp[0], qp[0], fmaf(qp[1], qp[1], qp[2] * qp[2]));
        const int qg = b * NQ + q0 + tid;
        float4* dst = (float4*)&g_c[half][qg][0];
        dst[0] = make_float4(b0, __int_as_float(k0), b1, __int_as_float(k1));
        dst[1] = make_float4(b2, __int_as_float(k2), qq, 0.0f);
    }
}

// ============================ Kernel 2 ==================================
// One warp per 4 queries: all candidate loads up front (MLP 16,
// warp-uniform), 4 independent branchless merges + single-reciprocal
// weights, then 12 independent coalesced gathers.
__global__ __launch_bounds__(TPB2)
void knn_finish_kernel(const float* __restrict__ v_k,
                       float* __restrict__ out)
{
    const int b    = blockIdx.y;
    const int warp = threadIdx.x >> 5;
    const int lane = threadIdx.x & 31;
    const int qg0  = b * NQ + blockIdx.x * QPC2 + warp * QW;

    // hoisted candidate loads: 16 warp-uniform LDG.128
    float4 A0[QW], B0[QW], A1[QW], B1[QW];
    #pragma unroll
    for (int t = 0; t < QW; ++t) {
        const float4* c0 = (const float4*)&g_c[0][qg0 + t][0];
        const float4* c1 = (const float4*)&g_c[1][qg0 + t][0];
        A0[t] = c0[0]; B0[t] = c0[1];
        A1[t] = c1[0]; B1[t] = c1[1];
    }

    const float4* vb = (const float4*)(v_k + (size_t)b * NK * CH);
    float4* ob = (float4*)(out + (size_t)qg0 * CH);

    #pragma unroll
    for (int t = 0; t < QW; ++t) {
        float d0 = A0[t].x, d1 = A0[t].z, d2 = B0[t].x;
        int   i0 = __float_as_int(A0[t].y), i1 = __float_as_int(A0[t].w),
              i2 = __float_as_int(B0[t].y);
        merge_tri_idx(A1[t].x, A1[t].z, B1[t].x,
                      __float_as_int(A1[t].y), __float_as_int(A1[t].w),
                      __float_as_int(B1[t].y),
                      d0, d1, d2, i0, i1, i2);

        float qq = B0[t].z;
        float e0 = fmaxf(d0 + qq, 1e-10f);
        float e1 = fmaxf(d1 + qq, 1e-10f);
        float e2 = fmaxf(d2 + qq, 1e-10f);
        float p01 = e0 * e1, p12 = e1 * e2, p20 = e2 * e0;
        float invS = 1.0f / (p01 + p12 + p20);
        float a0 = p12 * invS, a1 = p20 * invS, a2 = p01 * invS;

        float4 va = vb[i0 * (CH / 4) + lane];
        float4 vc = vb[i1 * (CH / 4) + lane];
        float4 vd = vb[i2 * (CH / 4) + lane];
        float4 r;
        r.x = a0 * va.x + a1 * vc.x + a2 * vd.x;
        r.y = a0 * va.y + a1 * vc.y + a2 * vd.y;
        r.z = a0 * va.z + a1 * vc.z + a2 * vd.z;
        r.w = a0 * va.w + a1 * vc.w + a2 * vd.w;
        ob[t * (CH / 4) + lane] = r;
    }
}

extern "C" void kernel_launch(void* const* d_in, const int* in_sizes, int n_in,
                              void* d_out, int out_size)
{
    const float* xyz_q = (const float*)d_in[0];   // [4, 8192, 3]
    const float* xyz_k = (const float*)d_in[1];   // [4, 2048, 3]
    const float* v_k   = (const float*)d_in[2];   // [4, 2048, 128]
    float* out = (float*)d_out;                   // [4, 8192, 128]

    dim3 grid1(NQ / QPB, 2, BATCH);    // (128, 2, 4) = 1024 CTAs
    knn_half_kernel<<<grid1, TPB1>>>(xyz_q, xyz_k);

    dim3 grid2(NQ / QPC2, BATCH);      // (256, 4) = 1024 CTAs, 4 q/warp
    knn_finish_kernel<<<grid2, TPB2>>>(v_k, out);
}